// round 9
// baseline (speedup 1.0000x reference)
#include <cuda_runtime.h>
#include <cstdint>

#define BROWS 32768
#define D0 1024
#define D1 512
#define D2 256

#define CAP 512           // smem-compacted dynamic elems per row (max expected ~430)
#define ELEMS_LANE 26     // scalar elements per lane, 16 lanes/row -> 416 in regs
#define REG_ELEMS 416
#define K_OVF 4           // per-lane register overflow slots beyond CAP
#define EPSC 1e-6f

// Small precomputed tables (~12 KB static total)
__device__ __align__(16) float g_s0[D0];
__device__ __align__(16) float g_s1[D1];
__device__ __align__(16) float g_s1s[D1];
__device__ __align__(16) float g_P[D1 + 1];
__device__ __align__(16) float g_Q[D1 + 1];

// Dynamic smem layout (floats): [s1s 512][P 513][Q 513][pad][16 rows x (w CAP | mt CAP)]
#define SM_S1S   0
#define SM_P     512
#define SM_Q     1025
#define SM_PAIRS 1540
#define SM_FLOATS (SM_PAIRS + 16 * 2 * CAP)   // 17924 floats = 71696 bytes

__device__ __forceinline__ float warp_sum(float s) {
    #pragma unroll
    for (int o = 16; o; o >>= 1) s += __shfl_xor_sync(0xFFFFFFFFu, s, o);
    return s;
}
__device__ __forceinline__ float rcp_approx(float v) {
    float r;
    asm("rcp.approx.f32 %0, %1;" : "=f"(r) : "f"(v));
    return r;
}

// ---------------------------------------------------------------------------
// Kernel 1: row sums of W0 and W1
// ---------------------------------------------------------------------------
__global__ void rowsum_kernel(const float* __restrict__ W0,
                              const float* __restrict__ W1) {
    int warp = (blockIdx.x * blockDim.x + threadIdx.x) >> 5;
    int lane = threadIdx.x & 31;
    if (warp < D0) {
        const float* row = W0 + (size_t)warp * D1;
        float s = 0.0f;
        #pragma unroll
        for (int k = 0; k < D1 / 32; k++) s += row[lane + 32 * k];
        s = warp_sum(s);
        if (lane == 0) g_s0[warp] = s;
    } else if (warp < D0 + D1) {
        int j = warp - D0;
        const float* row = W1 + (size_t)j * D2;
        float s = 0.0f;
        #pragma unroll
        for (int k = 0; k < D2 / 32; k++) s += row[lane + 32 * k];
        s = warp_sum(s);
        if (lane == 0) g_s1[j] = s;
    }
}

// ---------------------------------------------------------------------------
// Kernel 1b: sort s1 + prefix tables (cur1 = a0*P[i] + a1*Q[i])
// ---------------------------------------------------------------------------
__global__ void sort_prefix_kernel() {
    __shared__ float a[D1];
    __shared__ float b[D1];
    int tid = threadIdx.x;

    a[tid] = g_s1[tid];
    __syncthreads();
    for (int k = 2; k <= D1; k <<= 1) {
        for (int j = k >> 1; j > 0; j >>= 1) {
            int ixj = tid ^ j;
            if (ixj > tid) {
                bool up = ((tid & k) == 0);
                float x = a[tid], y = a[ixj];
                if ((x > y) == up) { a[tid] = y; a[ixj] = x; }
            }
            __syncthreads();
        }
    }
    float v = a[tid];
    for (int off = 1; off < D1; off <<= 1) {
        b[tid] = v;
        __syncthreads();
        if (tid >= off) v += b[tid - off];
        __syncthreads();
    }
    b[tid] = v;
    __syncthreads();

    g_s1s[tid] = a[tid];
    float ST = b[D1 - 1];
    for (int i = tid; i <= D1; i += D1) {
        float Si = (i == 0) ? 0.0f : b[i - 1];
        g_P[i] = (float)(2 * i - D1) * (1.0f / 256.0f);
        g_Q[i] = (ST - 2.0f * Si) * (1.0f / 256.0f);
    }
}

// ---------------------------------------------------------------------------
// Kernel 2: fused preprocessing + SNN time loop.
// 256 threads / 8 warps / 16 rows per block. 16 lanes per row, 2 rows per warp.
// Scalar math: FFMA + FADD with free |src| modifier (fabsf folds into FADD).
// ---------------------------------------------------------------------------
__global__ __launch_bounds__(256, 3)
void snn_kernel(const float* __restrict__ x,
                const int* __restrict__ ts_ptr,
                float* __restrict__ out) {
    extern __shared__ float sm[];

    const int warp = threadIdx.x >> 5;
    const int lane = threadIdx.x & 31;
    const int half = lane >> 4;          // 0 = row A, 1 = row B
    const int r    = lane & 15;          // lane index within the row group
    const int bufrow = warp * 2 + half;  // 0..15
    const int row  = blockIdx.x * 16 + bufrow;
    const unsigned halfmask = half ? 0xFFFF0000u : 0x0000FFFFu;
    const int tsteps = ts_ptr[0];

    float* wb = sm + SM_PAIRS + bufrow * (2 * CAP);        // w buffer  [CAP]
    float* mb = wb + CAP;                                  // mt buffer [CAP]

    // Load lookup tables
    for (int i = threadIdx.x; i < D1; i += 256) sm[SM_S1S + i] = g_s1s[i];
    for (int i = threadIdx.x; i <= D1; i += 256) {
        sm[SM_P + i] = g_P[i];
        sm[SM_Q + i] = g_Q[i];
    }

    // ---- Pass 1: classify 64 elements per lane; accumulate C, D; flag dynamics ----
    const float4* xrow4 = reinterpret_cast<const float4*>(x + (size_t)row * D0);
    const float4* s04   = reinterpret_cast<const float4*>(g_s0);

    float C = 0.0f, Dv = 0.0f;
    unsigned long long flags = 0ULL;
    int cnt_lane = 0;

    for (int i = 0; i < 16; i++) {
        float4 xv = xrow4[r + 16 * i];
        float4 sv = __ldg(&s04[r + 16 * i]);
        const float* xp = &xv.x;
        const float* sp = &sv.x;
        #pragma unroll
        for (int k = 0; k < 4; k++) {
            float s = sp[k], xx = xp[k];
            float w = fabsf(s);
            float t = (s < 0.0f) ? -xx : xx;
            if (t < -EPSC * w)             { C -= t; Dv += w; }
            else if (t > (1.0f + EPSC) * w){ C += t; Dv -= w; }
            else { flags |= 1ULL << (i * 4 + k); cnt_lane++; }
        }
    }
    // width-16 reductions (two rows independent)
    #pragma unroll
    for (int o = 8; o; o >>= 1) {
        C  += __shfl_xor_sync(0xFFFFFFFFu, C,  o, 16);
        Dv += __shfl_xor_sync(0xFFFFFFFFu, Dv, o, 16);
    }
    // width-16 exclusive prefix of dynamic counts
    int incl = cnt_lane;
    #pragma unroll
    for (int o = 1; o < 16; o <<= 1) {
        int n = __shfl_up_sync(0xFFFFFFFFu, incl, o, 16);
        if (r >= o) incl += n;
    }
    int pos = incl - cnt_lane;
    int cnt = __shfl_sync(0xFFFFFFFFu, incl, 15, 16);

    // ---- Pass 2: re-read and write compacted (w, mt) into the row buffer ----
    float ovf_w[K_OVF], ovf_m[K_OVF];
    int novf = 0;
    for (int i = 0; i < 16; i++) {
        if (!((flags >> (i * 4)) & 0xFULL)) continue;
        float4 xv = xrow4[r + 16 * i];
        float4 sv = __ldg(&s04[r + 16 * i]);
        const float* xp = &xv.x;
        const float* sp = &sv.x;
        #pragma unroll
        for (int k = 0; k < 4; k++) {
            if (flags & (1ULL << (i * 4 + k))) {
                float s = sp[k], xx = xp[k];
                float w = fabsf(s);
                float mt = (s < 0.0f) ? xx : -xx;   // -t
                if (pos < CAP) { wb[pos] = w; mb[pos] = mt; }
                else if (novf < K_OVF) { ovf_w[novf] = w; ovf_m[novf] = mt; novf++; }
                pos++;
            }
        }
    }
    // zero-fill [cnt, REG_ELEMS) so unused register slots contribute 0
    for (int idx = cnt + r; idx < REG_ELEMS; idx += 16) {
        wb[idx] = 0.0f;
        mb[idx] = 0.0f;
    }
    __syncthreads();

    // ---- Pull 416 elements/row into registers (scalar floats) ----
    float wreg[ELEMS_LANE], mreg[ELEMS_LANE];
    #pragma unroll
    for (int i = 0; i < ELEMS_LANE; i++) {
        int k = r + 16 * i;
        wreg[i] = wb[k];
        mreg[i] = mb[k];
    }

    const float probe1 = sm[SM_S1S + (r << 5)];
    const int sCnt = cnt < CAP ? cnt : CAP;
    const bool has_ovf = (cnt > REG_ELEMS);

    float v0 = 0.0f, a0 = 0.0f, v1 = 0.0f, a1 = 0.0f;
    float itf1 = 1.0f;

    for (int t = 0; t < tsteps; t++) {
        const float tf  = itf1 - 1.0f;
        const float inv = rcp_approx(itf1);

        // ---- Layer 0: cur0 = (2/1024)*(C + a0*D + sum_dyn |w*a0 + mt|) ----
        // FFMA + FADD-with-|src| (abs folds into the add) = 2 slots per element
        float acc0 = 0.0f, acc1 = 0.0f, acc2 = 0.0f, acc3 = 0.0f;
        #pragma unroll
        for (int i = 0; i + 3 < ELEMS_LANE; i += 4) {
            acc0 += fabsf(fmaf(wreg[i],     a0, mreg[i]));
            acc1 += fabsf(fmaf(wreg[i + 1], a0, mreg[i + 1]));
            acc2 += fabsf(fmaf(wreg[i + 2], a0, mreg[i + 2]));
            acc3 += fabsf(fmaf(wreg[i + 3], a0, mreg[i + 3]));
        }
        acc0 += fabsf(fmaf(wreg[24], a0, mreg[24]));
        acc1 += fabsf(fmaf(wreg[25], a0, mreg[25]));
        float part = (acc0 + acc1) + (acc2 + acc3);

        if (has_ovf) {
            for (int e = REG_ELEMS + r; e < sCnt; e += 16)
                part += fabsf(fmaf(wb[e], a0, mb[e]));
            for (int k = 0; k < novf; k++)
                part += fabsf(fmaf(ovf_w[k], a0, ovf_m[k]));
        }

        #pragma unroll
        for (int o = 8; o; o >>= 1)
            part += __shfl_xor_sync(0xFFFFFFFFu, part, o, 16);

        float cur0 = fmaf(a0, Dv, C + part) * (2.0f / (float)D0);

        v0 = fmaf(0.5f, v0, cur0);
        float sp0 = (v0 >= 1.0f) ? 1.0f : 0.0f;
        v0 = (v0 >= 1.0f) ? 0.0f : v0;
        a0 = fmaf(a0, tf, sp0) * inv;

        // ---- Layer 1: i = #{j : a1*s1s[j] <= a0}; cur1 = a0*P[i] + a1*Q[i] ----
        unsigned b1 = __ballot_sync(0xFFFFFFFFu, a1 * probe1 <= a0);
        int cnt1 = __popc(b1 & halfmask);
        int seg = (cnt1 > 0 ? cnt1 - 1 : 0) << 5;
        float p2 = sm[SM_S1S + seg + 2 * r];
        unsigned b2 = __ballot_sync(0xFFFFFFFFu, a1 * p2 <= a0);
        int c2 = __popc(b2 & halfmask);
        int j = seg + 2 * c2 - 1;
        j = j < 0 ? 0 : j;
        int i1 = j + ((a1 * sm[SM_S1S + j] <= a0) ? 1 : 0);
        i1 = (cnt1 == 0) ? 0 : i1;
        float cur1 = fmaf(a0, sm[SM_P + i1], a1 * sm[SM_Q + i1]);

        v1 = fmaf(0.5f, v1, cur1);
        float sp1 = (v1 >= 1.0f) ? 1.0f : 0.0f;
        v1 = (v1 >= 1.0f) ? 0.0f : v1;
        a1 = fmaf(a1, tf, sp1) * inv;

        itf1 += 1.0f;
    }

    // Output: row = a1 replicated across 256 features (4 float4 per lane)
    float4 o4 = make_float4(a1, a1, a1, a1);
    float4* orow = reinterpret_cast<float4*>(out + (size_t)row * D2);
    #pragma unroll
    for (int q = 0; q < 4; q++) orow[r + 16 * q] = o4;
}

// ---------------------------------------------------------------------------
// Launch
// ---------------------------------------------------------------------------
extern "C" void kernel_launch(void* const* d_in, const int* in_sizes, int n_in,
                              void* d_out, int out_size) {
    const float* x  = (const float*)d_in[0];   // [32768, 1024]
    const float* W0 = (const float*)d_in[1];   // [1024, 512]
    const float* W1 = (const float*)d_in[2];   // [512, 256]
    const int*   ts = (const int*)d_in[3];     // scalar time_steps
    float* out = (float*)d_out;                // [32768, 256]

    const int smem_bytes = SM_FLOATS * 4;      // 71696 B
    cudaFuncSetAttribute(snn_kernel,
                         cudaFuncAttributeMaxDynamicSharedMemorySize, smem_bytes);

    rowsum_kernel<<<192, 256>>>(W0, W1);
    sort_prefix_kernel<<<1, 512>>>();
    snn_kernel<<<BROWS / 16, 256, smem_bytes>>>(x, ts, out);
}